// round 1
// baseline (speedup 1.0000x reference)
#include <cuda_runtime.h>

#define NN 100000
#define EE 800000
#define DD 64
#define HH 4
#define CC 64
#define HC 256

// ---- scratch (static device globals: allocation-free) ----
__device__ float g_q[(size_t)NN * HC];
__device__ float g_k[(size_t)NN * HC];
__device__ float g_v[(size_t)NN * HC];
__device__ float g_skip[(size_t)NN * DD];
__device__ float g_agg[(size_t)NN * HC];
__device__ float g_denom[(size_t)NN * HH];
__device__ float g_h[(size_t)NN * DD];

// ---- zero the accumulators (agg + denom) ----
__global__ void zero_accum() {
    int i = blockIdx.x * blockDim.x + threadIdx.x;   // grid covers NN*HC
    g_agg[i] = 0.0f;
    if (i < NN * HH) g_denom[i] = 0.0f;
}

// ---- fused QKV + skip GEMM: X[nrows,64] @ {Wq,Wk,Wv(64x256), Ws(64x64)} ----
// grid: (ceil(nrows/64), 13). blockIdx.y: 0-3 q, 4-7 k, 8-11 v, 12 skip.
__global__ void __launch_bounds__(256) gemm_kernel(
    const float* __restrict__ Xext, int useGh,
    const float* __restrict__ Wq, const float* __restrict__ bq,
    const float* __restrict__ Wk, const float* __restrict__ bk,
    const float* __restrict__ Wv, const float* __restrict__ bv,
    const float* __restrict__ Ws, const float* __restrict__ bs,
    int nrows)
{
    const float* X = useGh ? g_h : Xext;
    __shared__ float Xs[64][65];   // [k][row]  (transposed X tile)
    __shared__ float Wt[64][68];   // [k][col]

    int bc = blockIdx.y;
    int row0 = blockIdx.x * 64;
    const float* W; const float* bias; float* out; int ld; int col0;
    if (bc < 4)       { W = Wq; bias = bq; out = g_q;    ld = 256; col0 = bc * 64; }
    else if (bc < 8)  { W = Wk; bias = bk; out = g_k;    ld = 256; col0 = (bc - 4) * 64; }
    else if (bc < 12) { W = Wv; bias = bv; out = g_v;    ld = 256; col0 = (bc - 8) * 64; }
    else              { W = Ws; bias = bs; out = g_skip; ld = 64;  col0 = 0; }

    int tid = threadIdx.x;
#pragma unroll
    for (int j = 0; j < 4; j++) {
        int idx = tid + j * 256;     // 0..1023 float4 slots
        int r   = idx >> 4;          // 0..63
        int c4  = idx & 15;          // 0..15
        int gr  = row0 + r;
        float4 xv = make_float4(0.f, 0.f, 0.f, 0.f);
        if (gr < nrows)
            xv = *reinterpret_cast<const float4*>(X + (size_t)gr * 64 + c4 * 4);
        Xs[c4 * 4 + 0][r] = xv.x;
        Xs[c4 * 4 + 1][r] = xv.y;
        Xs[c4 * 4 + 2][r] = xv.z;
        Xs[c4 * 4 + 3][r] = xv.w;
        float4 wv = *reinterpret_cast<const float4*>(W + (size_t)r * ld + col0 + c4 * 4);
        *reinterpret_cast<float4*>(&Wt[r][c4 * 4]) = wv;
    }
    __syncthreads();

    int tx = tid & 15, ty = tid >> 4;
    float acc[4][4] = {};
#pragma unroll
    for (int kk = 0; kk < 64; kk++) {
        float a0 = Xs[kk][ty * 4 + 0];
        float a1 = Xs[kk][ty * 4 + 1];
        float a2 = Xs[kk][ty * 4 + 2];
        float a3 = Xs[kk][ty * 4 + 3];
        float4 b = *reinterpret_cast<const float4*>(&Wt[kk][tx * 4]);
        acc[0][0] += a0 * b.x; acc[0][1] += a0 * b.y; acc[0][2] += a0 * b.z; acc[0][3] += a0 * b.w;
        acc[1][0] += a1 * b.x; acc[1][1] += a1 * b.y; acc[1][2] += a1 * b.z; acc[1][3] += a1 * b.w;
        acc[2][0] += a2 * b.x; acc[2][1] += a2 * b.y; acc[2][2] += a2 * b.z; acc[2][3] += a2 * b.w;
        acc[3][0] += a3 * b.x; acc[3][1] += a3 * b.y; acc[3][2] += a3 * b.z; acc[3][3] += a3 * b.w;
    }

    float4 bb = *reinterpret_cast<const float4*>(bias + col0 + tx * 4);
#pragma unroll
    for (int i = 0; i < 4; i++) {
        int gr = row0 + ty * 4 + i;
        if (gr < nrows) {
            float4 o;
            o.x = acc[i][0] + bb.x;
            o.y = acc[i][1] + bb.y;
            o.z = acc[i][2] + bb.z;
            o.w = acc[i][3] + bb.w;
            *reinterpret_cast<float4*>(out + (size_t)gr * ld + col0 + tx * 4) = o;
        }
    }
}

// ---- fused edge pass: one warp per edge ----
// alpha[h] = dot(q[dst,h], k[src,h]) / 8; ex = exp(alpha)
// denom[dst,h] += ex; agg[dst,h,:] += ex * v[src,h,:]
__global__ void __launch_bounds__(256) edge_kernel(const int* __restrict__ ei) {
    int w = (blockIdx.x * blockDim.x + threadIdx.x) >> 5;
    int lane = threadIdx.x & 31;
    if (w >= EE) return;
    int s = ei[w];
    int d = ei[EE + w];

    const float4* qd = reinterpret_cast<const float4*>(g_q) + (size_t)d * 64;
    const float4* ks = reinterpret_cast<const float4*>(g_k) + (size_t)s * 64;
    float4 a0 = qd[lane * 2], a1 = qd[lane * 2 + 1];
    float4 b0 = ks[lane * 2], b1 = ks[lane * 2 + 1];
    float p = a0.x * b0.x + a0.y * b0.y + a0.z * b0.z + a0.w * b0.w
            + a1.x * b1.x + a1.y * b1.y + a1.z * b1.z + a1.w * b1.w;
    // reduce within 8-lane head groups (lane>>3 == head)
    p += __shfl_xor_sync(0xffffffffu, p, 1);
    p += __shfl_xor_sync(0xffffffffu, p, 2);
    p += __shfl_xor_sync(0xffffffffu, p, 4);
    float ex = __expf(p * 0.125f);   // 1/sqrt(64)

    if ((lane & 7) == 0)
        atomicAdd(&g_denom[(size_t)d * 4 + (lane >> 3)], ex);

    const float4* vs = reinterpret_cast<const float4*>(g_v) + (size_t)s * 64;
    float4 v0 = vs[lane * 2], v1 = vs[lane * 2 + 1];
    float* ad = g_agg + (size_t)d * 256 + lane * 8;
    atomicAdd(ad + 0, ex * v0.x);
    atomicAdd(ad + 1, ex * v0.y);
    atomicAdd(ad + 2, ex * v0.z);
    atomicAdd(ad + 3, ex * v0.w);
    atomicAdd(ad + 4, ex * v1.x);
    atomicAdd(ad + 5, ex * v1.y);
    atomicAdd(ad + 6, ex * v1.z);
    atomicAdd(ad + 7, ex * v1.w);
}

// ---- node epilogue: out = mean_h(agg/denom) + skip (+relu) ----
__global__ void __launch_bounds__(256) node_kernel(float* __restrict__ out_ext,
                                                   int to_gh, int relu) {
    int i = blockIdx.x * blockDim.x + threadIdx.x;  // over NN*64
    if (i >= NN * DD) return;
    int n = i >> 6, c = i & 63;
    float acc = 0.0f;
#pragma unroll
    for (int h = 0; h < 4; h++)
        acc += g_agg[(size_t)n * 256 + h * 64 + c] / (g_denom[(size_t)n * 4 + h] + 1e-16f);
    acc = acc * 0.25f + g_skip[i];
    if (relu) acc = fmaxf(acc, 0.0f);
    float* out = to_gh ? g_h : out_ext;
    out[i] = acc;
}

extern "C" void kernel_launch(void* const* d_in, const int* in_sizes, int n_in,
                              void* d_out, int out_size) {
    const float* x   = (const float*)d_in[0];
    const int*   ei  = (const int*)d_in[1];
    const float* Wq1 = (const float*)d_in[2];
    const float* bq1 = (const float*)d_in[3];
    const float* Wk1 = (const float*)d_in[4];
    const float* bk1 = (const float*)d_in[5];
    const float* Wv1 = (const float*)d_in[6];
    const float* bv1 = (const float*)d_in[7];
    const float* Ws1 = (const float*)d_in[8];
    const float* bs1 = (const float*)d_in[9];
    const float* Wq2 = (const float*)d_in[10];
    const float* bq2 = (const float*)d_in[11];
    const float* Wk2 = (const float*)d_in[12];
    const float* bk2 = (const float*)d_in[13];
    const float* Wv2 = (const float*)d_in[14];
    const float* bv2 = (const float*)d_in[15];
    const float* Ws2 = (const float*)d_in[16];
    const float* bs2 = (const float*)d_in[17];
    float* out = (float*)d_out;

    dim3 ggrid((NN + 63) / 64, 13);
    int zero_blocks = (NN * HC + 255) / 256;          // 100000
    int edge_blocks = (EE * 32 + 255) / 256;          // 100000
    int node_blocks = (NN * DD + 255) / 256;          // 25000

    // ---- layer 1 ----
    zero_accum<<<zero_blocks, 256>>>();
    gemm_kernel<<<ggrid, 256>>>(x, 0, Wq1, bq1, Wk1, bk1, Wv1, bv1, Ws1, bs1, NN);
    edge_kernel<<<edge_blocks, 256>>>(ei);
    node_kernel<<<node_blocks, 256>>>(nullptr, /*to_gh=*/1, /*relu=*/1);

    // ---- layer 2 ----
    zero_accum<<<zero_blocks, 256>>>();
    gemm_kernel<<<ggrid, 256>>>(nullptr, 1, Wq2, bq2, Wk2, bk2, Wv2, bv2, Ws2, bs2, NN);
    edge_kernel<<<edge_blocks, 256>>>(ei);
    node_kernel<<<node_blocks, 256>>>(out, /*to_gh=*/0, /*relu=*/0);
}

// round 2
// speedup vs baseline: 2.5708x; 2.5708x over previous
#include <cuda_runtime.h>

#define NN 100000
#define EE 800000
#define DD 64
#define HH 4
#define HC 256

// ---- scratch (static device globals: allocation-free) ----
__device__ float g_q[(size_t)NN * HC];
__device__ float g_k[(size_t)NN * HC];
__device__ float g_v[(size_t)NN * HC];
__device__ float g_skip[(size_t)NN * DD];
__device__ float g_h[(size_t)NN * DD];
__device__ int   g_cnt[NN];
__device__ int   g_indptr[NN + 1];
__device__ int   g_cursor[NN];
__device__ int   g_col[EE];

// ================= CSR build (per call, deterministic input) =================
__global__ void zero_cnt_kernel() {
    int i = blockIdx.x * blockDim.x + threadIdx.x;
    if (i < NN) g_cnt[i] = 0;
}

__global__ void hist_kernel(const int* __restrict__ ei) {
    int e = blockIdx.x * blockDim.x + threadIdx.x;
    if (e < EE) atomicAdd(&g_cnt[ei[EE + e]], 1);
}

// single-block exclusive scan over g_cnt -> g_indptr / g_cursor
__global__ void __launch_bounds__(1024) scan_kernel() {
    __shared__ int s_w[32];
    __shared__ int s_carry;
    int tid = threadIdx.x, lane = tid & 31, wid = tid >> 5;
    if (tid == 0) s_carry = 0;
    __syncthreads();
    const int CH = (NN + 1 + 1023) / 1024;
    for (int c = 0; c < CH; c++) {
        int i = c * 1024 + tid;
        int v = (i < NN) ? g_cnt[i] : 0;
        int x = v;
#pragma unroll
        for (int d = 1; d < 32; d <<= 1) {
            int t = __shfl_up_sync(0xffffffffu, x, d);
            if (lane >= d) x += t;
        }
        if (lane == 31) s_w[wid] = x;
        __syncthreads();
        int carry = s_carry;
        if (wid == 0) {
            int y = s_w[lane];
#pragma unroll
            for (int d = 1; d < 32; d <<= 1) {
                int t = __shfl_up_sync(0xffffffffu, y, d);
                if (lane >= d) y += t;
            }
            s_w[lane] = y;
        }
        __syncthreads();
        int offs = carry + (wid > 0 ? s_w[wid - 1] : 0);
        int excl = offs + x - v;
        if (i <= NN) {
            g_indptr[i] = excl;
            if (i < NN) g_cursor[i] = excl;
        }
        __syncthreads();
        if (tid == 0) s_carry = carry + s_w[31];
        __syncthreads();
    }
}

__global__ void scatter_kernel(const int* __restrict__ ei) {
    int e = blockIdx.x * blockDim.x + threadIdx.x;
    if (e < EE) {
        int d = ei[EE + e];
        int pos = atomicAdd(&g_cursor[d], 1);
        g_col[pos] = ei[e];
    }
}

// ===== fused QKV + skip GEMM: X[nrows,64] @ {Wq,Wk,Wv(64x256), Ws(64x64)} ====
// grid: (ceil(nrows/64), 13). blockIdx.y: 0-3 q, 4-7 k, 8-11 v, 12 skip.
__global__ void __launch_bounds__(256) gemm_kernel(
    const float* __restrict__ Xext, int useGh,
    const float* __restrict__ Wq, const float* __restrict__ bq,
    const float* __restrict__ Wk, const float* __restrict__ bk,
    const float* __restrict__ Wv, const float* __restrict__ bv,
    const float* __restrict__ Ws, const float* __restrict__ bs,
    int nrows)
{
    const float* X = useGh ? g_h : Xext;
    __shared__ float Xs[64][68];   // [k][row]  (transposed X tile)
    __shared__ float Wt[64][68];   // [k][col]

    int bc = blockIdx.y;
    int row0 = blockIdx.x * 64;
    const float* W; const float* bias; float* out; int ld; int col0;
    if (bc < 4)       { W = Wq; bias = bq; out = g_q;    ld = 256; col0 = bc * 64; }
    else if (bc < 8)  { W = Wk; bias = bk; out = g_k;    ld = 256; col0 = (bc - 4) * 64; }
    else if (bc < 12) { W = Wv; bias = bv; out = g_v;    ld = 256; col0 = (bc - 8) * 64; }
    else              { W = Ws; bias = bs; out = g_skip; ld = 64;  col0 = 0; }

    int tid = threadIdx.x;
#pragma unroll
    for (int j = 0; j < 4; j++) {
        int idx = tid + j * 256;     // 0..1023 float4 slots
        int r   = idx >> 4;          // 0..63
        int c4  = idx & 15;          // 0..15
        int gr  = row0 + r;
        float4 xv = make_float4(0.f, 0.f, 0.f, 0.f);
        if (gr < nrows)
            xv = *reinterpret_cast<const float4*>(X + (size_t)gr * 64 + c4 * 4);
        Xs[c4 * 4 + 0][r] = xv.x;
        Xs[c4 * 4 + 1][r] = xv.y;
        Xs[c4 * 4 + 2][r] = xv.z;
        Xs[c4 * 4 + 3][r] = xv.w;
        float4 wv = *reinterpret_cast<const float4*>(W + (size_t)r * ld + col0 + c4 * 4);
        *reinterpret_cast<float4*>(&Wt[r][c4 * 4]) = wv;
    }
    __syncthreads();

    int tx = tid & 15, ty = tid >> 4;
    float acc[4][4] = {};
#pragma unroll
    for (int kk = 0; kk < 64; kk++) {
        float4 a = *reinterpret_cast<const float4*>(&Xs[kk][ty * 4]);
        float4 b = *reinterpret_cast<const float4*>(&Wt[kk][tx * 4]);
        acc[0][0] += a.x * b.x; acc[0][1] += a.x * b.y; acc[0][2] += a.x * b.z; acc[0][3] += a.x * b.w;
        acc[1][0] += a.y * b.x; acc[1][1] += a.y * b.y; acc[1][2] += a.y * b.z; acc[1][3] += a.y * b.w;
        acc[2][0] += a.z * b.x; acc[2][1] += a.z * b.y; acc[2][2] += a.z * b.z; acc[2][3] += a.z * b.w;
        acc[3][0] += a.w * b.x; acc[3][1] += a.w * b.y; acc[3][2] += a.w * b.z; acc[3][3] += a.w * b.w;
    }

    float4 bb = *reinterpret_cast<const float4*>(bias + col0 + tx * 4);
#pragma unroll
    for (int i = 0; i < 4; i++) {
        int gr = row0 + ty * 4 + i;
        if (gr < nrows) {
            float4 o;
            o.x = acc[i][0] + bb.x;
            o.y = acc[i][1] + bb.y;
            o.z = acc[i][2] + bb.z;
            o.w = acc[i][3] + bb.w;
            *reinterpret_cast<float4*>(out + (size_t)gr * ld + col0 + tx * 4) = o;
        }
    }
}

// ====== fused attention + epilogue: one warp per destination node ======
// lane = h*8 + m  (head h = lane>>3, channel slice m = lane&7 covering 8 ch)
// out[n] = 0.25 * sum_h (sum_e ex*v) / (sum_e ex + 1e-16) + skip[n]  (+relu)
__global__ void __launch_bounds__(256) attn_kernel(float* __restrict__ out_ext,
                                                   int to_gh, int relu) {
    int n = (blockIdx.x * blockDim.x + threadIdx.x) >> 5;
    if (n >= NN) return;
    int lane = threadIdx.x & 31;
    int h = lane >> 3, m = lane & 7;

    size_t qbase = (size_t)n * HC + h * 64 + m * 8;
    float4 q0 = *reinterpret_cast<const float4*>(g_q + qbase);
    float4 q1 = *reinterpret_cast<const float4*>(g_q + qbase + 4);

    float acc[8] = {0.f, 0.f, 0.f, 0.f, 0.f, 0.f, 0.f, 0.f};
    float den = 0.f;

    int e0 = g_indptr[n], e1 = g_indptr[n + 1];
    for (int e = e0; e < e1; e++) {
        int s = g_col[e];
        size_t base = (size_t)s * HC + h * 64 + m * 8;
        float4 k0 = *reinterpret_cast<const float4*>(g_k + base);
        float4 k1 = *reinterpret_cast<const float4*>(g_k + base + 4);
        float p = q0.x * k0.x + q0.y * k0.y + q0.z * k0.z + q0.w * k0.w
                + q1.x * k1.x + q1.y * k1.y + q1.z * k1.z + q1.w * k1.w;
        p += __shfl_xor_sync(0xffffffffu, p, 1);
        p += __shfl_xor_sync(0xffffffffu, p, 2);
        p += __shfl_xor_sync(0xffffffffu, p, 4);
        float ex = __expf(p * 0.125f);   // 1/sqrt(64)

        float4 v0 = *reinterpret_cast<const float4*>(g_v + base);
        float4 v1 = *reinterpret_cast<const float4*>(g_v + base + 4);
        acc[0] += ex * v0.x; acc[1] += ex * v0.y;
        acc[2] += ex * v0.z; acc[3] += ex * v0.w;
        acc[4] += ex * v1.x; acc[5] += ex * v1.y;
        acc[6] += ex * v1.z; acc[7] += ex * v1.w;
        den += ex;
    }

    float inv = 1.0f / (den + 1e-16f);
#pragma unroll
    for (int j = 0; j < 8; j++) {
        float r = acc[j] * inv;
        r += __shfl_xor_sync(0xffffffffu, r, 8);
        r += __shfl_xor_sync(0xffffffffu, r, 16);
        acc[j] = r * 0.25f;
    }

    if (h == 0) {   // lanes 0..7 write channels m*8..m*8+7
        float* out = to_gh ? g_h : out_ext;
        size_t ob = (size_t)n * DD + m * 8;
        float4 s0 = *reinterpret_cast<const float4*>(g_skip + ob);
        float4 s1 = *reinterpret_cast<const float4*>(g_skip + ob + 4);
        float4 o0, o1;
        o0.x = acc[0] + s0.x; o0.y = acc[1] + s0.y;
        o0.z = acc[2] + s0.z; o0.w = acc[3] + s0.w;
        o1.x = acc[4] + s1.x; o1.y = acc[5] + s1.y;
        o1.z = acc[6] + s1.z; o1.w = acc[7] + s1.w;
        if (relu) {
            o0.x = fmaxf(o0.x, 0.f); o0.y = fmaxf(o0.y, 0.f);
            o0.z = fmaxf(o0.z, 0.f); o0.w = fmaxf(o0.w, 0.f);
            o1.x = fmaxf(o1.x, 0.f); o1.y = fmaxf(o1.y, 0.f);
            o1.z = fmaxf(o1.z, 0.f); o1.w = fmaxf(o1.w, 0.f);
        }
        *reinterpret_cast<float4*>(out + ob)     = o0;
        *reinterpret_cast<float4*>(out + ob + 4) = o1;
    }
}

extern "C" void kernel_launch(void* const* d_in, const int* in_sizes, int n_in,
                              void* d_out, int out_size) {
    const float* x   = (const float*)d_in[0];
    const int*   ei  = (const int*)d_in[1];
    const float* Wq1 = (const float*)d_in[2];
    const float* bq1 = (const float*)d_in[3];
    const float* Wk1 = (const float*)d_in[4];
    const float* bk1 = (const float*)d_in[5];
    const float* Wv1 = (const float*)d_in[6];
    const float* bv1 = (const float*)d_in[7];
    const float* Ws1 = (const float*)d_in[8];
    const float* bs1 = (const float*)d_in[9];
    const float* Wq2 = (const float*)d_in[10];
    const float* bq2 = (const float*)d_in[11];
    const float* Wk2 = (const float*)d_in[12];
    const float* bk2 = (const float*)d_in[13];
    const float* Wv2 = (const float*)d_in[14];
    const float* bv2 = (const float*)d_in[15];
    const float* Ws2 = (const float*)d_in[16];
    const float* bs2 = (const float*)d_in[17];
    float* out = (float*)d_out;

    // ---- CSR by destination (rebuilt every call; graph-capturable) ----
    zero_cnt_kernel<<<(NN + 255) / 256, 256>>>();
    hist_kernel<<<(EE + 255) / 256, 256>>>(ei);
    scan_kernel<<<1, 1024>>>();
    scatter_kernel<<<(EE + 255) / 256, 256>>>(ei);

    dim3 ggrid((NN + 63) / 64, 13);
    int attn_blocks = (NN * 32 + 255) / 256;   // one warp per node

    // ---- layer 1 ----
    gemm_kernel<<<ggrid, 256>>>(x, 0, Wq1, bq1, Wk1, bk1, Wv1, bv1, Ws1, bs1, NN);
    attn_kernel<<<attn_blocks, 256>>>(nullptr, /*to_gh=*/1, /*relu=*/1);

    // ---- layer 2 ----
    gemm_kernel<<<ggrid, 256>>>(nullptr, 1, Wq2, bq2, Wk2, bk2, Wv2, bv2, Ws2, bs2, NN);
    attn_kernel<<<attn_blocks, 256>>>(out, /*to_gh=*/0, /*relu=*/0);
}